// round 11
// baseline (speedup 1.0000x reference)
#include <cuda_runtime.h>

#define N_EMB   512
#define EMB_D   64
#define NDP     32                 // d-pairs
#define HWSZ    4096
#define NTOK    131072
#define TPB     256
#define TILE_T  64                 // tokens per tile
#define NTILE   (NTOK / TILE_T)    // 2048
#define GRID_A  148
#define NREP    8

// Output packing (float32, reference tuple order)
#define OFF_RES 0ULL
#define OFF_ARG 8388608ULL
#define OFF_W   8519680ULL
#define OFF_CS  8552448ULL
#define OFF_EA  8552960ULL

// smem: wT [32][512] u64 | xT [32][64] u64 | ww [512] f32 | keys [64] u64
#define SM_WT_U64   (NDP * N_EMB)              // 16384
#define SM_XT_U64   (NDP * TILE_T)             // 2048
#define SMEM_BYTES  (SM_WT_U64 * 8 + SM_XT_U64 * 8 + N_EMB * 4 + TILE_T * 8)

__device__ float g_histR[NREP][N_EMB];
__device__ float g_esumR[NREP][EMB_D * N_EMB];
__device__ float g_ww[N_EMB];
__device__ unsigned long long g_wt2[SM_WT_U64];   // [dpair][j] packed f32x2
__device__ unsigned int g_work;
__device__ unsigned int g_done;

__device__ __forceinline__ unsigned long long ffma2(unsigned long long a,
                                                    unsigned long long b,
                                                    unsigned long long c) {
    unsigned long long d;
    asm("fma.rn.f32x2 %0, %1, %2, %3;" : "=l"(d) : "l"(a), "l"(b), "l"(c));
    return d;
}

__device__ __forceinline__ unsigned long long pack2(float lo, float hi) {
    unsigned long long r;
    asm("mov.b64 %0, {%1, %2};" : "=l"(r)
        : "r"(__float_as_uint(lo)), "r"(__float_as_uint(hi)));
    return r;
}

__device__ __forceinline__ void unpack2(unsigned long long v, float& lo, float& hi) {
    unsigned int a, b;
    asm("mov.b64 {%0, %1}, %2;" : "=r"(a), "=r"(b) : "l"(v));
    lo = __uint_as_float(a);
    hi = __uint_as_float(b);
}

// ---------------------------------------------------------------------------
// prep: zero replicated scratch, packed transposed codebook, ||w||^2, counters
// ---------------------------------------------------------------------------
__global__ void prep_kernel(const float* __restrict__ w) {
    int idx = blockIdx.x * blockDim.x + threadIdx.x;   // 0..32767
    if (idx == 0) { g_work = 0u; g_done = 0u; }
    if (idx < EMB_D * N_EMB) {
        #pragma unroll
        for (int r = 0; r < NREP; r++) g_esumR[r][idx] = 0.0f;
    }
    if (idx < SM_WT_U64) {
        int dd = idx >> 9;
        int j  = idx & (N_EMB - 1);
        g_wt2[idx] = pack2(w[(2 * dd) * N_EMB + j], w[(2 * dd + 1) * N_EMB + j]);
    }
    if (idx < N_EMB) {
        #pragma unroll
        for (int r = 0; r < NREP; r++) g_histR[r][idx] = 0.0f;
        float s = 0.0f;
        #pragma unroll
        for (int d = 0; d < EMB_D; d++) {
            float v = w[d * N_EMB + idx];
            s = __fadd_rn(s, __fmul_rn(v, v));
        }
        g_ww[idx] = s;
    }
}

// ---------------------------------------------------------------------------
// assign: tiled scan, 256 thr = (tx 0..31 codewords) x (ty 0..7 token groups).
// Tile = 64 tokens. Each thread: 8 tokens x 4 consecutive codewords; 4 passes.
// Keys in registers across passes; shfl butterfly min; no spill (cap 255).
// ---------------------------------------------------------------------------
extern __shared__ unsigned long long smem_u64[];

__global__ void __launch_bounds__(TPB, 1)
assign_kernel(const float* __restrict__ x,
              const float* __restrict__ cs_in,
              const float* __restrict__ ea_in,
              float* __restrict__ out) {
    unsigned long long* wTs  = smem_u64;                    // [32][512]
    unsigned long long* xTs  = smem_u64 + SM_WT_U64;        // [32][64]
    float*              ww_s = (float*)(xTs + SM_XT_U64);   // [512]
    unsigned long long* keys = (unsigned long long*)(ww_s + N_EMB); // [64]

    __shared__ int s_chunk;
    __shared__ unsigned int s_rank;

    int tid  = threadIdx.x;
    int tx   = tid & 31;
    int ty   = tid >> 5;
    int tloc = ty * 8;          // this warp's 8 tokens
    int rep  = blockIdx.x & (NREP - 1);
    float* histR = g_histR[rep];
    float* esumR = g_esumR[rep];

    // Stage packed codebook + ww (coalesced, conflict-free)
    {
        const ulonglong2* src = (const ulonglong2*)g_wt2;
        ulonglong2* dst = (ulonglong2*)wTs;
        #pragma unroll
        for (int i = 0; i < (SM_WT_U64 / 2) / TPB; i++)   // 32 iters
            dst[i * TPB + tid] = src[i * TPB + tid];
        ww_s[tid]       = g_ww[tid];
        ww_s[tid + 256] = g_ww[tid + 256];
    }

    for (;;) {
        __syncthreads();
        if (tid == 0) s_chunk = (int)atomicAdd(&g_work, 1u);
        __syncthreads();
        int tile = s_chunk;
        if (tile >= NTILE) break;

        int t0g = tile * TILE_T;            // tile never crosses a batch
        int b   = t0g >> 12;
        int hw0 = t0g & (HWSZ - 1);
        const float* xb = x + (size_t)b * EMB_D * HWSZ + hw0;

        // Load x tile transposed into smem: xT[dd][t] (coalesced over t)
        #pragma unroll
        for (int k = 0; k < SM_XT_U64 / TPB; k++) {     // 8 iters
            int idx = tid + TPB * k;
            int dd  = idx >> 6;
            int t   = idx & (TILE_T - 1);
            xTs[idx] = pack2(xb[(2 * dd) * HWSZ + t], xb[(2 * dd + 1) * HWSZ + t]);
        }
        __syncthreads();

        unsigned long long bk[8];
        #pragma unroll
        for (int t = 0; t < 8; t++) bk[t] = ~0ULL;

        #pragma unroll 1
        for (int pass = 0; pass < 4; pass++) {
            int jb = pass * 128 + 4 * tx;            // 4 consecutive codewords
            const unsigned long long* wbase = wTs + jb;
            const unsigned long long* xbase = xTs + tloc;

            unsigned long long acc[8][4];
            #pragma unroll
            for (int t = 0; t < 8; t++)
                #pragma unroll
                for (int k = 0; k < 4; k++) acc[t][k] = 0ULL;

            #pragma unroll
            for (int dd = 0; dd < NDP; dd++) {
                ulonglong2 w01 = *(const ulonglong2*)(wbase + dd * N_EMB);
                ulonglong2 w23 = *(const ulonglong2*)(wbase + dd * N_EMB + 2);
                ulonglong2 x01 = *(const ulonglong2*)(xbase + dd * TILE_T);
                ulonglong2 x23 = *(const ulonglong2*)(xbase + dd * TILE_T + 2);
                ulonglong2 x45 = *(const ulonglong2*)(xbase + dd * TILE_T + 4);
                ulonglong2 x67 = *(const ulonglong2*)(xbase + dd * TILE_T + 6);

                unsigned long long xv[8] = { x01.x, x01.y, x23.x, x23.y,
                                             x45.x, x45.y, x67.x, x67.y };
                unsigned long long wv[4] = { w01.x, w01.y, w23.x, w23.y };

                #pragma unroll
                for (int t = 0; t < 8; t++) {
                    acc[t][0] = ffma2(xv[t], wv[0], acc[t][0]);
                    acc[t][1] = ffma2(xv[t], wv[1], acc[t][1]);
                    acc[t][2] = ffma2(xv[t], wv[2], acc[t][2]);
                    acc[t][3] = ffma2(xv[t], wv[3], acc[t][3]);
                }
            }

            // distances + sortable-key min (min dist, tie -> min j)
            float4 wq = *(const float4*)(ww_s + jb);
            float wwv[4] = { wq.x, wq.y, wq.z, wq.w };
            #pragma unroll
            for (int t = 0; t < 8; t++) {
                unsigned long long best = bk[t];
                #pragma unroll
                for (int k = 0; k < 4; k++) {
                    float lo, hi;
                    unpack2(acc[t][k], lo, hi);
                    float d = __fmaf_rn(-2.0f, __fadd_rn(lo, hi), wwv[k]);
                    unsigned int s = __float_as_uint(d);
                    s = (s & 0x80000000u) ? ~s : (s | 0x80000000u);
                    unsigned long long key =
                        ((unsigned long long)s << 32) | (unsigned int)(jb + k);
                    if (key < best) best = key;
                }
                bk[t] = best;
            }
        }

        // warp butterfly min (each token's full j-space lives in this warp)
        #pragma unroll
        for (int off = 16; off > 0; off >>= 1) {
            #pragma unroll
            for (int t = 0; t < 8; t++) {
                unsigned long long o = __shfl_xor_sync(0xFFFFFFFFu, bk[t], off);
                if (o < bk[t]) bk[t] = o;
            }
        }
        if (tx == 0) {
            #pragma unroll
            for (int t = 0; t < 8; t++) keys[tloc + t] = bk[t];
        }
        __syncthreads();

        // ----- epilogue: 4 d-groups x 64 tokens across 256 threads -----
        int tk = tid & (TILE_T - 1);
        int dg = tid >> 6;                 // 0..3, 8 d-pairs each
        int bi = (int)(keys[tk] & 0xFFFFFFFFULL);

        if (dg == 0) {                     // warps 0,1: uniform branch
            out[OFF_ARG + (size_t)(t0g + tk)] = (float)bi;
            unsigned int m = __match_any_sync(0xFFFFFFFFu, bi);
            if ((int)(__ffs(m) - 1) == tx)
                atomicAdd(&histR[bi], (float)__popc(m));
        }

        float* ro = out + (size_t)b * EMB_D * HWSZ + hw0 + tk;
        #pragma unroll
        for (int q = 0; q < 8; q++) {
            int dd = dg * 8 + q;
            float lo, hi;
            unpack2(wTs[dd * N_EMB + bi], lo, hi);
            ro[(2 * dd)     * HWSZ] = lo;
            ro[(2 * dd + 1) * HWSZ] = hi;
            float xlo, xhi;
            unpack2(xTs[dd * TILE_T + tk], xlo, xhi);
            atomicAdd(&esumR[(2 * dd)     * N_EMB + bi], xlo);
            atomicAdd(&esumR[(2 * dd + 1) * N_EMB + bi], xhi);
        }
    }

    // ------- merged finalize: last CTA does the EMA update -------
    __threadfence();
    __syncthreads();
    if (tid == 0) s_rank = atomicAdd(&g_done, 1u);
    __syncthreads();
    if (s_rank == GRID_A - 1) {
        float* red = (float*)smem_u64;

        const float DEC  = 0.99f;
        const float OMD  = (float)(1.0 - 0.99);
        const float EPSF = (float)1e-5;
        const float NEPS = (float)(N_EMB * 1e-5);

        float ncs0, ncs1;
        {
            float n0 = 0.0f, n1 = 0.0f;
            #pragma unroll
            for (int r = 0; r < NREP; r++) {
                n0 += g_histR[r][tid];
                n1 += g_histR[r][tid + 256];
            }
            if (n0 == 0.0f) n0 = 1.0f;
            if (n1 == 0.0f) n1 = 1.0f;
            ncs0 = __fadd_rn(__fmul_rn(DEC, cs_in[tid]), __fmul_rn(OMD, n0));
            ncs1 = __fadd_rn(__fmul_rn(DEC, cs_in[tid + 256]), __fmul_rn(OMD, n1));
        }

        __syncthreads();
        red[tid] = ncs0 + ncs1;
        __syncthreads();
        #pragma unroll
        for (int s = 128; s > 0; s >>= 1) {
            if (tid < s) red[tid] += red[tid + s];
            __syncthreads();
        }
        float n = red[0];

        float csn0 = __fmul_rn(__fdiv_rn(__fadd_rn(ncs0, EPSF),
                                         __fadd_rn(n, NEPS)), n);
        float csn1 = __fmul_rn(__fdiv_rn(__fadd_rn(ncs1, EPSF),
                                         __fadd_rn(n, NEPS)), n);

        out[OFF_CS + tid]       = ncs0;
        out[OFF_CS + tid + 256] = ncs1;

        for (int d = 0; d < EMB_D; d++) {
            int i0 = d * N_EMB + tid;
            int i1 = i0 + 256;
            float s0 = 0.0f, s1 = 0.0f;
            #pragma unroll
            for (int r = 0; r < NREP; r++) {
                s0 += g_esumR[r][i0];
                s1 += g_esumR[r][i1];
            }
            float e0 = __fadd_rn(__fmul_rn(DEC, ea_in[i0]), __fmul_rn(OMD, s0));
            float e1 = __fadd_rn(__fmul_rn(DEC, ea_in[i1]), __fmul_rn(OMD, s1));
            out[OFF_EA + i0] = e0;
            out[OFF_EA + i1] = e1;
            out[OFF_W  + i0] = __fdiv_rn(e0, csn0);
            out[OFF_W  + i1] = __fdiv_rn(e1, csn1);
        }
    }
}

// ---------------------------------------------------------------------------
extern "C" void kernel_launch(void* const* d_in, const int* in_sizes, int n_in,
                              void* d_out, int out_size) {
    const float* x  = (const float*)d_in[0];
    const float* w  = (const float*)d_in[1];
    const float* cs = (const float*)d_in[2];
    const float* ea = (const float*)d_in[3];
    float* out = (float*)d_out;

    cudaFuncSetAttribute(assign_kernel,
                         cudaFuncAttributeMaxDynamicSharedMemorySize, SMEM_BYTES);

    prep_kernel<<<128, 256>>>(w);
    assign_kernel<<<GRID_A, TPB, SMEM_BYTES>>>(x, cs, ea, out);
}

// round 12
// speedup vs baseline: 1.6556x; 1.6556x over previous
#include <cuda_runtime.h>

#define N_EMB   512
#define EMB_D   64
#define HWSZ    4096
#define NTOK    131072
#define TPB     384
#define NCHUNK  342                     // 341 full chunks of 384 + partial (128)
#define GRID_A  148
#define NREP    8

// Output packing (float32, reference tuple order)
#define OFF_RES 0ULL
#define OFF_ARG 8388608ULL
#define OFF_W   8519680ULL
#define OFF_CS  8552448ULL
#define OFF_EA  8552960ULL

#define SMEM_BYTES ((N_EMB * EMB_D + 2 * N_EMB) * 4)   // codebook + ww + scratch

__device__ float g_histR[NREP][N_EMB];
__device__ float g_esumR[NREP][EMB_D * N_EMB];
__device__ float g_ww[N_EMB];
__device__ float g_wt[N_EMB * EMB_D];   // weight transposed: [j][d]
__device__ unsigned int g_work;
__device__ unsigned int g_done;

__device__ __forceinline__ unsigned long long ffma2(unsigned long long a,
                                                    unsigned long long b,
                                                    unsigned long long c) {
    unsigned long long d;
    asm("fma.rn.f32x2 %0, %1, %2, %3;" : "=l"(d) : "l"(a), "l"(b), "l"(c));
    return d;
}

__device__ __forceinline__ unsigned long long fadd2(unsigned long long a,
                                                    unsigned long long b) {
    unsigned long long d;
    asm("add.rn.f32x2 %0, %1, %2;" : "=l"(d) : "l"(a), "l"(b));
    return d;
}

__device__ __forceinline__ unsigned long long pack2(float lo, float hi) {
    unsigned long long r;
    asm("mov.b64 %0, {%1, %2};" : "=l"(r)
        : "r"(__float_as_uint(lo)), "r"(__float_as_uint(hi)));
    return r;
}

__device__ __forceinline__ void unpack2(unsigned long long v, float& lo, float& hi) {
    unsigned int a, b;
    asm("mov.b64 {%0, %1}, %2;" : "=r"(a), "=r"(b) : "l"(v));
    lo = __uint_as_float(a);
    hi = __uint_as_float(b);
}

// ---------------------------------------------------------------------------
// prep
// ---------------------------------------------------------------------------
__global__ void prep_kernel(const float* __restrict__ w) {
    int idx = blockIdx.x * blockDim.x + threadIdx.x;
    if (idx == 0) { g_work = 0u; g_done = 0u; }
    if (idx < EMB_D * N_EMB) {
        #pragma unroll
        for (int r = 0; r < NREP; r++) g_esumR[r][idx] = 0.0f;
        int j = idx >> 6;
        int d = idx & 63;
        g_wt[idx] = w[d * N_EMB + j];
    }
    if (idx < N_EMB) {
        #pragma unroll
        for (int r = 0; r < NREP; r++) g_histR[r][idx] = 0.0f;
        float s = 0.0f;
        #pragma unroll
        for (int d = 0; d < EMB_D; d++) {
            float v = w[d * N_EMB + idx];
            s = __fadd_rn(s, __fmul_rn(v, v));
        }
        g_ww[idx] = s;
    }
}

// ---------------------------------------------------------------------------
// assign: 384 thr (3 warps/SMSP), T=1 token/thread (xp = 64 regs), J=4.
// ~60 spare regs for ptxas load batching. Persistent work-steal.
// ---------------------------------------------------------------------------
extern __shared__ float smem_dyn[];

__global__ void __launch_bounds__(TPB, 1)
assign_kernel(const float* __restrict__ x,
              const float* __restrict__ cs_in,
              const float* __restrict__ ea_in,
              float* __restrict__ out) {
    float* w_s  = smem_dyn;                     // [512][64] j-major
    float* ww_s = smem_dyn + N_EMB * EMB_D;     // [512]
    __shared__ int s_chunk;
    __shared__ unsigned int s_rank;

    int tid  = threadIdx.x;
    int lane = tid & 31;
    int rep  = blockIdx.x & (NREP - 1);
    float* histR = g_histR[rep];
    float* esumR = g_esumR[rep];

    // Stage transposed weight once per CTA: coalesced, conflict-free
    {
        const float4* src = (const float4*)g_wt;
        float4* dst = (float4*)w_s;
        for (int i = tid; i < N_EMB * EMB_D / 4; i += TPB)
            dst[i] = src[i];
        for (int j = tid; j < N_EMB; j += TPB)
            ww_s[j] = g_ww[j];
    }

    for (;;) {
        __syncthreads();
        if (tid == 0) s_chunk = (int)atomicAdd(&g_work, 1u);
        __syncthreads();
        int c = s_chunk;
        if (c >= NCHUNK) break;

        int t0 = c * TPB + tid;
        bool vA = (t0 < NTOK);
        int t0c = vA ? t0 : (NTOK - 1);
        int b0  = t0c >> 12;
        int hw0 = t0c & (HWSZ - 1);
        const float* xa_p = x + (size_t)b0 * EMB_D * HWSZ + hw0;

        // Token features -> packed f32x2 (64 registers)
        unsigned long long xp[EMB_D / 2];
        #pragma unroll
        for (int i = 0; i < EMB_D / 2; i++)
            xp[i] = pack2(xa_p[(2 * i) * HWSZ], xa_p[(2 * i + 1) * HWSZ]);

        float best = 3.4e38f;
        int   bi   = 0;

        #pragma unroll 1
        for (int j0 = 0; j0 < N_EMB; j0 += 4) {
            const ulonglong2* r0 = (const ulonglong2*)(w_s + (j0 + 0) * EMB_D);
            const ulonglong2* r1 = (const ulonglong2*)(w_s + (j0 + 1) * EMB_D);
            const ulonglong2* r2 = (const ulonglong2*)(w_s + (j0 + 2) * EMB_D);
            const ulonglong2* r3 = (const ulonglong2*)(w_s + (j0 + 3) * EMB_D);

            unsigned long long a0e = 0ULL, a0o = 0ULL;
            unsigned long long a1e = 0ULL, a1o = 0ULL;
            unsigned long long a2e = 0ULL, a2o = 0ULL;
            unsigned long long a3e = 0ULL, a3o = 0ULL;

            #pragma unroll
            for (int q = 0; q < EMB_D / 4; q++) {
                ulonglong2 v0 = r0[q];
                ulonglong2 v1 = r1[q];
                ulonglong2 v2 = r2[q];
                ulonglong2 v3 = r3[q];
                unsigned long long xe = xp[2 * q];
                unsigned long long xo = xp[2 * q + 1];
                a0e = ffma2(xe, v0.x, a0e);  a0o = ffma2(xo, v0.y, a0o);
                a1e = ffma2(xe, v1.x, a1e);  a1o = ffma2(xo, v1.y, a1o);
                a2e = ffma2(xe, v2.x, a2e);  a2o = ffma2(xo, v2.y, a2o);
                a3e = ffma2(xe, v3.x, a3e);  a3o = ffma2(xo, v3.y, a3o);
            }

            float lo, hi;
            unpack2(fadd2(a0e, a0o), lo, hi);
            float d0 = __fmaf_rn(-2.0f, __fadd_rn(lo, hi), ww_s[j0 + 0]);
            unpack2(fadd2(a1e, a1o), lo, hi);
            float d1 = __fmaf_rn(-2.0f, __fadd_rn(lo, hi), ww_s[j0 + 1]);
            unpack2(fadd2(a2e, a2o), lo, hi);
            float d2 = __fmaf_rn(-2.0f, __fadd_rn(lo, hi), ww_s[j0 + 2]);
            unpack2(fadd2(a3e, a3o), lo, hi);
            float d3 = __fmaf_rn(-2.0f, __fadd_rn(lo, hi), ww_s[j0 + 3]);

            // strict < ascending j => first-min tie-break (jnp.argmin)
            if (d0 < best) { best = d0; bi = j0 + 0; }
            if (d1 < best) { best = d1; bi = j0 + 1; }
            if (d2 < best) { best = d2; bi = j0 + 2; }
            if (d3 < best) { best = d3; bi = j0 + 3; }
        }

        if (vA) {
            out[OFF_ARG + (size_t)t0] = (float)bi;

            // quantized result from smem codebook
            float* ro = out + (size_t)b0 * EMB_D * HWSZ + hw0;
            const float4* wrow = (const float4*)(w_s + bi * EMB_D);
            #pragma unroll
            for (int i = 0; i < EMB_D / 4; i++) {
                float4 v = wrow[i];
                ro[(4 * i + 0) * HWSZ] = v.x;
                ro[(4 * i + 1) * HWSZ] = v.y;
                ro[(4 * i + 2) * HWSZ] = v.z;
                ro[(4 * i + 3) * HWSZ] = v.w;
            }
        }

        // hist: warp-aggregated under validity mask
        {
            unsigned int act = __ballot_sync(0xFFFFFFFFu, vA);
            unsigned int m = __match_any_sync(0xFFFFFFFFu, bi) & act;
            if (vA && (int)(__ffs(m) - 1) == lane)
                atomicAdd(&histR[bi], (float)__popc(m));
        }

        // esum: replicated accumulators
        if (vA) {
            #pragma unroll
            for (int i = 0; i < EMB_D / 2; i++) {
                float lo, hi;
                unpack2(xp[i], lo, hi);
                atomicAdd(&esumR[(2 * i)     * N_EMB + bi], lo);
                atomicAdd(&esumR[(2 * i + 1) * N_EMB + bi], hi);
            }
        }
    }

    // ------- merged finalize: last CTA does the EMA update -------
    __threadfence();
    __syncthreads();
    if (tid == 0) s_rank = atomicAdd(&g_done, 1u);
    __syncthreads();
    if (s_rank == GRID_A - 1) {
        float* red   = smem_dyn;              // [512]
        float* ncs_s = smem_dyn + N_EMB;      // [512]

        const float DEC  = 0.99f;
        const float OMD  = (float)(1.0 - 0.99);
        const float EPSF = (float)1e-5;
        const float NEPS = (float)(N_EMB * 1e-5);

        __syncthreads();
        for (int j = tid; j < N_EMB; j += TPB) {
            float n0 = 0.0f;
            #pragma unroll
            for (int r = 0; r < NREP; r++) n0 += g_histR[r][j];
            if (n0 == 0.0f) n0 = 1.0f;
            float ncs = __fadd_rn(__fmul_rn(DEC, cs_in[j]), __fmul_rn(OMD, n0));
            ncs_s[j] = ncs;
            red[j]   = ncs;
        }
        __syncthreads();
        #pragma unroll
        for (int s = N_EMB / 2; s > 0; s >>= 1) {
            if (tid < s) red[tid] += red[tid + s];
            __syncthreads();
        }
        float n = red[0];

        for (int j = tid; j < N_EMB; j += TPB) {
            float ncs = ncs_s[j];
            float csn = __fmul_rn(__fdiv_rn(__fadd_rn(ncs, EPSF),
                                            __fadd_rn(n, NEPS)), n);
            out[OFF_CS + j] = ncs;
            for (int d = 0; d < EMB_D; d++) {
                int idx = d * N_EMB + j;
                float s0 = 0.0f;
                #pragma unroll
                for (int r = 0; r < NREP; r++) s0 += g_esumR[r][idx];
                float e = __fadd_rn(__fmul_rn(DEC, ea_in[idx]),
                                    __fmul_rn(OMD, s0));
                out[OFF_EA + idx] = e;
                out[OFF_W  + idx] = __fdiv_rn(e, csn);
            }
        }
    }
}

// ---------------------------------------------------------------------------
extern "C" void kernel_launch(void* const* d_in, const int* in_sizes, int n_in,
                              void* d_out, int out_size) {
    const float* x  = (const float*)d_in[0];
    const float* w  = (const float*)d_in[1];
    const float* cs = (const float*)d_in[2];
    const float* ea = (const float*)d_in[3];
    float* out = (float*)d_out;

    cudaFuncSetAttribute(assign_kernel,
                         cudaFuncAttributeMaxDynamicSharedMemorySize, SMEM_BYTES);

    prep_kernel<<<128, 256>>>(w);
    assign_kernel<<<GRID_A, TPB, SMEM_BYTES>>>(x, cs, ea, out);
}

// round 13
// speedup vs baseline: 2.0665x; 1.2482x over previous
#include <cuda_runtime.h>

#define N_EMB   512
#define EMB_D   64
#define HWSZ    4096
#define NTOK    131072
#define TPB     256
#define GRID_A  148
#define NREP    8

#define NBIG    192                 // big chunks: 512 tokens (T=2)
#define NSMALL  128                 // small chunks: 256 tokens (T=1)
#define NCHUNK  (NBIG + NSMALL)     // 320
#define SMALL_BASE (NBIG * 512)     // 98304

// Output packing (float32, reference tuple order)
#define OFF_RES 0ULL
#define OFF_ARG 8388608ULL
#define OFF_W   8519680ULL
#define OFF_CS  8552448ULL
#define OFF_EA  8552960ULL

#define SMEM_BYTES ((N_EMB * EMB_D + N_EMB) * 4)   // 133120 B

__device__ float g_histR[NREP][N_EMB];
__device__ float g_esumR[NREP][EMB_D * N_EMB];
__device__ float g_ww[N_EMB];
__device__ float g_wt[N_EMB * EMB_D];   // weight transposed: [j][d]
__device__ unsigned int g_work;
__device__ unsigned int g_done;

__device__ __forceinline__ unsigned long long ffma2(unsigned long long a,
                                                    unsigned long long b,
                                                    unsigned long long c) {
    unsigned long long d;
    asm("fma.rn.f32x2 %0, %1, %2, %3;" : "=l"(d) : "l"(a), "l"(b), "l"(c));
    return d;
}

__device__ __forceinline__ unsigned long long fadd2(unsigned long long a,
                                                    unsigned long long b) {
    unsigned long long d;
    asm("add.rn.f32x2 %0, %1, %2;" : "=l"(d) : "l"(a), "l"(b));
    return d;
}

__device__ __forceinline__ unsigned long long pack2(float lo, float hi) {
    unsigned long long r;
    asm("mov.b64 %0, {%1, %2};" : "=l"(r)
        : "r"(__float_as_uint(lo)), "r"(__float_as_uint(hi)));
    return r;
}

__device__ __forceinline__ void unpack2(unsigned long long v, float& lo, float& hi) {
    unsigned int a, b;
    asm("mov.b64 {%0, %1}, %2;" : "=r"(a), "=r"(b) : "l"(v));
    lo = __uint_as_float(a);
    hi = __uint_as_float(b);
}

// ---------------------------------------------------------------------------
// prep
// ---------------------------------------------------------------------------
__global__ void prep_kernel(const float* __restrict__ w) {
    int idx = blockIdx.x * blockDim.x + threadIdx.x;
    if (idx == 0) { g_work = 0u; g_done = 0u; }
    if (idx < EMB_D * N_EMB) {
        #pragma unroll
        for (int r = 0; r < NREP; r++) g_esumR[r][idx] = 0.0f;
        int j = idx >> 6;
        int d = idx & 63;
        g_wt[idx] = w[d * N_EMB + j];
    }
    if (idx < N_EMB) {
        #pragma unroll
        for (int r = 0; r < NREP; r++) g_histR[r][idx] = 0.0f;
        float s = 0.0f;
        #pragma unroll
        for (int d = 0; d < EMB_D; d++) {
            float v = w[d * N_EMB + idx];
            s = __fadd_rn(s, __fmul_rn(v, v));
        }
        g_ww[idx] = s;
    }
}

// ---------------------------------------------------------------------------
// assign: R8 core + mixed-granularity work-steal (192 x 512-token T=2 chunks,
// then 128 x 256-token T=1 chunks to smooth the straggler tail).
// ---------------------------------------------------------------------------
extern __shared__ float smem_dyn[];

__global__ void __launch_bounds__(TPB, 1)
assign_kernel(const float* __restrict__ x,
              const float* __restrict__ cs_in,
              const float* __restrict__ ea_in,
              float* __restrict__ out) {
    float* w_s  = smem_dyn;                     // [512][64] j-major
    float* ww_s = smem_dyn + N_EMB * EMB_D;     // [512]
    __shared__ int s_chunk;
    __shared__ unsigned int s_rank;

    int tid  = threadIdx.x;
    int lane = tid & 31;
    int rep  = blockIdx.x & (NREP - 1);
    float* histR = g_histR[rep];
    float* esumR = g_esumR[rep];

    // Stage transposed weight once per CTA: coalesced, conflict-free
    {
        const float4* src = (const float4*)g_wt;
        float4* dst = (float4*)w_s;
        #pragma unroll
        for (int i = 0; i < (N_EMB * EMB_D / 4) / TPB; i++)
            dst[i * TPB + tid] = src[i * TPB + tid];
        ww_s[tid]       = g_ww[tid];
        ww_s[tid + 256] = g_ww[tid + 256];
    }

    for (;;) {
        __syncthreads();
        if (tid == 0) s_chunk = (int)atomicAdd(&g_work, 1u);
        __syncthreads();
        int c = s_chunk;
        if (c >= NCHUNK) break;

        if (c < NBIG) {
            // ================= big chunk: 512 tokens, T=2 =================
            int t0 = c * 512 + tid;            // token A; token B = t0+256
            int b0 = t0 >> 12;
            int hw0 = t0 & (HWSZ - 1);
            const float* xa_p = x + (size_t)b0 * EMB_D * HWSZ + hw0;

            unsigned long long xpa[EMB_D / 2];
            unsigned long long xpb[EMB_D / 2];
            #pragma unroll
            for (int i = 0; i < EMB_D / 2; i++) {
                xpa[i] = pack2(xa_p[(2 * i) * HWSZ],       xa_p[(2 * i + 1) * HWSZ]);
                xpb[i] = pack2(xa_p[(2 * i) * HWSZ + 256], xa_p[(2 * i + 1) * HWSZ + 256]);
            }

            float bestA = 3.4e38f, bestB = 3.4e38f;
            int   biA = 0, biB = 0;

            #pragma unroll 1
            for (int j0 = 0; j0 < N_EMB; j0 += 2) {
                const ulonglong2* r0 = (const ulonglong2*)(w_s + (j0 + 0) * EMB_D);
                const ulonglong2* r1 = (const ulonglong2*)(w_s + (j0 + 1) * EMB_D);

                unsigned long long a0Ae = 0ULL, a0Ao = 0ULL, a0Be = 0ULL, a0Bo = 0ULL;
                unsigned long long a1Ae = 0ULL, a1Ao = 0ULL, a1Be = 0ULL, a1Bo = 0ULL;

                #pragma unroll
                for (int q = 0; q < EMB_D / 4; q++) {
                    ulonglong2 v0 = r0[q];
                    ulonglong2 v1 = r1[q];
                    unsigned long long xaE = xpa[2 * q], xaO = xpa[2 * q + 1];
                    unsigned long long xbE = xpb[2 * q], xbO = xpb[2 * q + 1];
                    a0Ae = ffma2(xaE, v0.x, a0Ae);  a0Ao = ffma2(xaO, v0.y, a0Ao);
                    a0Be = ffma2(xbE, v0.x, a0Be);  a0Bo = ffma2(xbO, v0.y, a0Bo);
                    a1Ae = ffma2(xaE, v1.x, a1Ae);  a1Ao = ffma2(xaO, v1.y, a1Ao);
                    a1Be = ffma2(xbE, v1.x, a1Be);  a1Bo = ffma2(xbO, v1.y, a1Bo);
                }

                float lo, hi;
                float w0 = ww_s[j0], w1 = ww_s[j0 + 1];
                unpack2(fadd2(a0Ae, a0Ao), lo, hi);
                float d0A = __fmaf_rn(-2.0f, __fadd_rn(lo, hi), w0);
                unpack2(fadd2(a1Ae, a1Ao), lo, hi);
                float d1A = __fmaf_rn(-2.0f, __fadd_rn(lo, hi), w1);
                unpack2(fadd2(a0Be, a0Bo), lo, hi);
                float d0B = __fmaf_rn(-2.0f, __fadd_rn(lo, hi), w0);
                unpack2(fadd2(a1Be, a1Bo), lo, hi);
                float d1B = __fmaf_rn(-2.0f, __fadd_rn(lo, hi), w1);

                if (d0A < bestA) { bestA = d0A; biA = j0;     }
                if (d1A < bestA) { bestA = d1A; biA = j0 + 1; }
                if (d0B < bestB) { bestB = d0B; biB = j0;     }
                if (d1B < bestB) { bestB = d1B; biB = j0 + 1; }
            }

            out[OFF_ARG + (size_t)t0]       = (float)biA;
            out[OFF_ARG + (size_t)t0 + 256] = (float)biB;

            {
                float* ro = out + (size_t)b0 * EMB_D * HWSZ + hw0;
                const float4* wrowA = (const float4*)(w_s + biA * EMB_D);
                const float4* wrowB = (const float4*)(w_s + biB * EMB_D);
                #pragma unroll
                for (int i = 0; i < EMB_D / 4; i++) {
                    float4 va = wrowA[i];
                    float4 vb = wrowB[i];
                    ro[(4 * i + 0) * HWSZ]       = va.x;
                    ro[(4 * i + 1) * HWSZ]       = va.y;
                    ro[(4 * i + 2) * HWSZ]       = va.z;
                    ro[(4 * i + 3) * HWSZ]       = va.w;
                    ro[(4 * i + 0) * HWSZ + 256] = vb.x;
                    ro[(4 * i + 1) * HWSZ + 256] = vb.y;
                    ro[(4 * i + 2) * HWSZ + 256] = vb.z;
                    ro[(4 * i + 3) * HWSZ + 256] = vb.w;
                }
            }

            {
                unsigned int mA = __match_any_sync(0xFFFFFFFFu, biA);
                if ((int)(__ffs(mA) - 1) == lane)
                    atomicAdd(&histR[biA], (float)__popc(mA));
                unsigned int mB = __match_any_sync(0xFFFFFFFFu, biB);
                if ((int)(__ffs(mB) - 1) == lane)
                    atomicAdd(&histR[biB], (float)__popc(mB));
            }

            #pragma unroll
            for (int i = 0; i < EMB_D / 2; i++) {
                float lo, hi;
                unpack2(xpa[i], lo, hi);
                atomicAdd(&esumR[(2 * i)     * N_EMB + biA], lo);
                atomicAdd(&esumR[(2 * i + 1) * N_EMB + biA], hi);
                unpack2(xpb[i], lo, hi);
                atomicAdd(&esumR[(2 * i)     * N_EMB + biB], lo);
                atomicAdd(&esumR[(2 * i + 1) * N_EMB + biB], hi);
            }
        } else {
            // ================ small chunk: 256 tokens, T=1 ================
            int t0 = SMALL_BASE + (c - NBIG) * 256 + tid;
            int b0 = t0 >> 12;
            int hw0 = t0 & (HWSZ - 1);
            const float* xa_p = x + (size_t)b0 * EMB_D * HWSZ + hw0;

            unsigned long long xp[EMB_D / 2];
            #pragma unroll
            for (int i = 0; i < EMB_D / 2; i++)
                xp[i] = pack2(xa_p[(2 * i) * HWSZ], xa_p[(2 * i + 1) * HWSZ]);

            float best = 3.4e38f;
            int   bi   = 0;

            #pragma unroll 1
            for (int j0 = 0; j0 < N_EMB; j0 += 4) {
                const ulonglong2* r0 = (const ulonglong2*)(w_s + (j0 + 0) * EMB_D);
                const ulonglong2* r1 = (const ulonglong2*)(w_s + (j0 + 1) * EMB_D);
                const ulonglong2* r2 = (const ulonglong2*)(w_s + (j0 + 2) * EMB_D);
                const ulonglong2* r3 = (const ulonglong2*)(w_s + (j0 + 3) * EMB_D);

                unsigned long long a0e = 0ULL, a0o = 0ULL;
                unsigned long long a1e = 0ULL, a1o = 0ULL;
                unsigned long long a2e = 0ULL, a2o = 0ULL;
                unsigned long long a3e = 0ULL, a3o = 0ULL;

                #pragma unroll
                for (int q = 0; q < EMB_D / 4; q++) {
                    ulonglong2 v0 = r0[q];
                    ulonglong2 v1 = r1[q];
                    ulonglong2 v2 = r2[q];
                    ulonglong2 v3 = r3[q];
                    unsigned long long xe = xp[2 * q];
                    unsigned long long xo = xp[2 * q + 1];
                    a0e = ffma2(xe, v0.x, a0e);  a0o = ffma2(xo, v0.y, a0o);
                    a1e = ffma2(xe, v1.x, a1e);  a1o = ffma2(xo, v1.y, a1o);
                    a2e = ffma2(xe, v2.x, a2e);  a2o = ffma2(xo, v2.y, a2o);
                    a3e = ffma2(xe, v3.x, a3e);  a3o = ffma2(xo, v3.y, a3o);
                }

                float lo, hi;
                unpack2(fadd2(a0e, a0o), lo, hi);
                float d0 = __fmaf_rn(-2.0f, __fadd_rn(lo, hi), ww_s[j0 + 0]);
                unpack2(fadd2(a1e, a1o), lo, hi);
                float d1 = __fmaf_rn(-2.0f, __fadd_rn(lo, hi), ww_s[j0 + 1]);
                unpack2(fadd2(a2e, a2o), lo, hi);
                float d2 = __fmaf_rn(-2.0f, __fadd_rn(lo, hi), ww_s[j0 + 2]);
                unpack2(fadd2(a3e, a3o), lo, hi);
                float d3 = __fmaf_rn(-2.0f, __fadd_rn(lo, hi), ww_s[j0 + 3]);

                if (d0 < best) { best = d0; bi = j0 + 0; }
                if (d1 < best) { best = d1; bi = j0 + 1; }
                if (d2 < best) { best = d2; bi = j0 + 2; }
                if (d3 < best) { best = d3; bi = j0 + 3; }
            }

            out[OFF_ARG + (size_t)t0] = (float)bi;

            {
                float* ro = out + (size_t)b0 * EMB_D * HWSZ + hw0;
                const float4* wrow = (const float4*)(w_s + bi * EMB_D);
                #pragma unroll
                for (int i = 0; i < EMB_D / 4; i++) {
                    float4 v = wrow[i];
                    ro[(4 * i + 0) * HWSZ] = v.x;
                    ro[(4 * i + 1) * HWSZ] = v.y;
                    ro[(4 * i + 2) * HWSZ] = v.z;
                    ro[(4 * i + 3) * HWSZ] = v.w;
                }
            }

            {
                unsigned int m = __match_any_sync(0xFFFFFFFFu, bi);
                if ((int)(__ffs(m) - 1) == lane)
                    atomicAdd(&histR[bi], (float)__popc(m));
            }

            #pragma unroll
            for (int i = 0; i < EMB_D / 2; i++) {
                float lo, hi;
                unpack2(xp[i], lo, hi);
                atomicAdd(&esumR[(2 * i)     * N_EMB + bi], lo);
                atomicAdd(&esumR[(2 * i + 1) * N_EMB + bi], hi);
            }
        }
    }

    // ------- merged finalize: last CTA does the EMA update -------
    __threadfence();
    __syncthreads();
    if (tid == 0) s_rank = atomicAdd(&g_done, 1u);
    __syncthreads();
    if (s_rank == GRID_A - 1) {
        float* red = smem_dyn;

        const float DEC  = 0.99f;
        const float OMD  = (float)(1.0 - 0.99);
        const float EPSF = (float)1e-5;
        const float NEPS = (float)(N_EMB * 1e-5);

        float ncs0, ncs1;
        {
            float n0 = 0.0f, n1 = 0.0f;
            #pragma unroll
            for (int r = 0; r < NREP; r++) {
                n0 += g_histR[r][tid];
                n1 += g_histR[r][tid + 256];
            }
            if (n0 == 0.0f) n0 = 1.0f;
            if (n1 == 0.0f) n1 = 1.0f;
            ncs0 = __fadd_rn(__fmul_rn(DEC, cs_in[tid]), __fmul_rn(OMD, n0));
            ncs1 = __fadd_rn(__fmul_rn(DEC, cs_in[tid + 256]), __fmul_rn(OMD, n1));
        }

        __syncthreads();
        red[tid] = ncs0 + ncs1;
        __syncthreads();
        #pragma unroll
        for (int s = 128; s > 0; s >>= 1) {
            if (tid < s) red[tid] += red[tid + s];
            __syncthreads();
        }
        float n = red[0];

        float csn0 = __fmul_rn(__fdiv_rn(__fadd_rn(ncs0, EPSF),
                                         __fadd_rn(n, NEPS)), n);
        float csn1 = __fmul_rn(__fdiv_rn(__fadd_rn(ncs1, EPSF),
                                         __fadd_rn(n, NEPS)), n);

        out[OFF_CS + tid]       = ncs0;
        out[OFF_CS + tid + 256] = ncs1;

        for (int d = 0; d < EMB_D; d++) {
            int i0 = d * N_EMB + tid;
            int i1 = i0 + 256;
            float s0 = 0.0f, s1 = 0.0f;
            #pragma unroll
            for (int r = 0; r < NREP; r++) {
                s0 += g_esumR[r][i0];
                s1 += g_esumR[r][i1];
            }
            float e0 = __fadd_rn(__fmul_rn(DEC, ea_in[i0]), __fmul_rn(OMD, s0));
            float e1 = __fadd_rn(__fmul_rn(DEC, ea_in[i1]), __fmul_rn(OMD, s1));
            out[OFF_EA + i0] = e0;
            out[OFF_EA + i1] = e1;
            out[OFF_W  + i0] = __fdiv_rn(e0, csn0);
            out[OFF_W  + i1] = __fdiv_rn(e1, csn1);
        }
    }
}

// ---------------------------------------------------------------------------
extern "C" void kernel_launch(void* const* d_in, const int* in_sizes, int n_in,
                              void* d_out, int out_size) {
    const float* x  = (const float*)d_in[0];
    const float* w  = (const float*)d_in[1];
    const float* cs = (const float*)d_in[2];
    const float* ea = (const float*)d_in[3];
    float* out = (float*)d_out;

    cudaFuncSetAttribute(assign_kernel,
                         cudaFuncAttributeMaxDynamicSharedMemorySize, SMEM_BYTES);

    prep_kernel<<<128, 256>>>(w);
    assign_kernel<<<GRID_A, TPB, SMEM_BYTES>>>(x, cs, ea, out);
}

// round 15
// speedup vs baseline: 2.3712x; 1.1474x over previous
#include <cuda_runtime.h>

#define N_EMB   512
#define EMB_D   64
#define HWSZ    4096
#define NTOK    131072
#define TPB     256
#define TOKS_PER_CHUNK (TPB * 2)          // T=2 tokens per thread
#define NCHUNK  (NTOK / TOKS_PER_CHUNK)   // 256
#define GRID_A  148
#define NREP    8

// Output packing (float32, reference tuple order)
#define OFF_RES 0ULL
#define OFF_ARG 8388608ULL
#define OFF_W   8519680ULL
#define OFF_CS  8552448ULL
#define OFF_EA  8552960ULL

#define SMEM_BYTES ((N_EMB * EMB_D + N_EMB) * 4)   // 133120 B

__device__ float g_histR[NREP][N_EMB];
__device__ float g_esumR[NREP][EMB_D * N_EMB];
__device__ float g_ww[N_EMB];
__device__ float g_wt[N_EMB * EMB_D];   // weight transposed: [j][d]
__device__ unsigned int g_work;
__device__ unsigned int g_done;

__device__ __forceinline__ unsigned long long ffma2(unsigned long long a,
                                                    unsigned long long b,
                                                    unsigned long long c) {
    unsigned long long d;
    asm("fma.rn.f32x2 %0, %1, %2, %3;" : "=l"(d) : "l"(a), "l"(b), "l"(c));
    return d;
}

__device__ __forceinline__ unsigned long long fadd2(unsigned long long a,
                                                    unsigned long long b) {
    unsigned long long d;
    asm("add.rn.f32x2 %0, %1, %2;" : "=l"(d) : "l"(a), "l"(b));
    return d;
}

__device__ __forceinline__ unsigned long long pack2(float lo, float hi) {
    unsigned long long r;
    asm("mov.b64 %0, {%1, %2};" : "=l"(r)
        : "r"(__float_as_uint(lo)), "r"(__float_as_uint(hi)));
    return r;
}

__device__ __forceinline__ void unpack2(unsigned long long v, float& lo, float& hi) {
    unsigned int a, b;
    asm("mov.b64 {%0, %1}, %2;" : "=r"(a), "=r"(b) : "l"(v));
    lo = __uint_as_float(a);
    hi = __uint_as_float(b);
}

// ---------------------------------------------------------------------------
// prep: zero replicated scratch, transpose weight, ||w||^2, reset counters
// ---------------------------------------------------------------------------
__global__ void prep_kernel(const float* __restrict__ w) {
    int idx = blockIdx.x * blockDim.x + threadIdx.x;
    if (idx == 0) { g_work = 0u; g_done = 0u; }
    if (idx < EMB_D * N_EMB) {
        #pragma unroll
        for (int r = 0; r < NREP; r++) g_esumR[r][idx] = 0.0f;
        int j = idx >> 6;
        int d = idx & 63;
        g_wt[idx] = w[d * N_EMB + j];
    }
    if (idx < N_EMB) {
        #pragma unroll
        for (int r = 0; r < NREP; r++) g_histR[r][idx] = 0.0f;
        float s = 0.0f;
        #pragma unroll
        for (int d = 0; d < EMB_D; d++) {
            float v = w[d * N_EMB + idx];
            s = __fadd_rn(s, __fmul_rn(v, v));
        }
        g_ww[idx] = s;
    }
}

// ---------------------------------------------------------------------------
// assign: R8 core with J=4 codewords/iteration (halves iteration-boundary
// drain cost), T=2 tokens/thread, warp-agg hist, NREP-replicated esum.
// ---------------------------------------------------------------------------
extern __shared__ float smem_dyn[];

__global__ void __launch_bounds__(TPB, 1)
assign_kernel(const float* __restrict__ x,
              const float* __restrict__ cs_in,
              const float* __restrict__ ea_in,
              float* __restrict__ out) {
    float* w_s  = smem_dyn;                     // [512][64] j-major
    float* ww_s = smem_dyn + N_EMB * EMB_D;     // [512]
    __shared__ int s_chunk;
    __shared__ unsigned int s_rank;

    int tid  = threadIdx.x;
    int lane = tid & 31;
    int rep  = blockIdx.x & (NREP - 1);
    float* histR = g_histR[rep];
    float* esumR = g_esumR[rep];

    // Stage transposed weight once per CTA: coalesced, conflict-free
    {
        const float4* src = (const float4*)g_wt;
        float4* dst = (float4*)w_s;
        #pragma unroll
        for (int i = 0; i < (N_EMB * EMB_D / 4) / TPB; i++)
            dst[i * TPB + tid] = src[i * TPB + tid];
        ww_s[tid]       = g_ww[tid];
        ww_s[tid + 256] = g_ww[tid + 256];
    }

    for (;;) {
        __syncthreads();
        if (tid == 0) s_chunk = (int)atomicAdd(&g_work, 1u);
        __syncthreads();
        int c = s_chunk;
        if (c >= NCHUNK) break;

        // chunk = 512 consecutive tokens, never crosses a batch
        int t0 = c * TOKS_PER_CHUNK + tid;     // token A; token B = t0+256
        int b0 = t0 >> 12;
        int hw0 = t0 & (HWSZ - 1);
        const float* xa_p = x + (size_t)b0 * EMB_D * HWSZ + hw0;

        unsigned long long xpa[EMB_D / 2];
        unsigned long long xpb[EMB_D / 2];
        #pragma unroll
        for (int i = 0; i < EMB_D / 2; i++) {
            xpa[i] = pack2(xa_p[(2 * i) * HWSZ],       xa_p[(2 * i + 1) * HWSZ]);
            xpb[i] = pack2(xa_p[(2 * i) * HWSZ + 256], xa_p[(2 * i + 1) * HWSZ + 256]);
        }

        float bestA = 3.4e38f, bestB = 3.4e38f;
        int   biA = 0, biB = 0;

        #pragma unroll 1
        for (int j0 = 0; j0 < N_EMB; j0 += 4) {
            const ulonglong2* r0 = (const ulonglong2*)(w_s + (j0 + 0) * EMB_D);
            const ulonglong2* r1 = (const ulonglong2*)(w_s + (j0 + 1) * EMB_D);
            const ulonglong2* r2 = (const ulonglong2*)(w_s + (j0 + 2) * EMB_D);
            const ulonglong2* r3 = (const ulonglong2*)(w_s + (j0 + 3) * EMB_D);

            // accumulators: [codeword][token][even/odd half] = 16 u64
            unsigned long long a0Ae = 0ULL, a0Ao = 0ULL, a0Be = 0ULL, a0Bo = 0ULL;
            unsigned long long a1Ae = 0ULL, a1Ao = 0ULL, a1Be = 0ULL, a1Bo = 0ULL;
            unsigned long long a2Ae = 0ULL, a2Ao = 0ULL, a2Be = 0ULL, a2Bo = 0ULL;
            unsigned long long a3Ae = 0ULL, a3Ao = 0ULL, a3Be = 0ULL, a3Bo = 0ULL;

            #pragma unroll
            for (int q = 0; q < EMB_D / 4; q++) {
                ulonglong2 v0 = r0[q];     // broadcast LDS.128
                ulonglong2 v1 = r1[q];
                ulonglong2 v2 = r2[q];
                ulonglong2 v3 = r3[q];
                unsigned long long xaE = xpa[2 * q], xaO = xpa[2 * q + 1];
                unsigned long long xbE = xpb[2 * q], xbO = xpb[2 * q + 1];
                a0Ae = ffma2(xaE, v0.x, a0Ae);  a0Ao = ffma2(xaO, v0.y, a0Ao);
                a0Be = ffma2(xbE, v0.x, a0Be);  a0Bo = ffma2(xbO, v0.y, a0Bo);
                a1Ae = ffma2(xaE, v1.x, a1Ae);  a1Ao = ffma2(xaO, v1.y, a1Ao);
                a1Be = ffma2(xbE, v1.x, a1Be);  a1Bo = ffma2(xbO, v1.y, a1Bo);
                a2Ae = ffma2(xaE, v2.x, a2Ae);  a2Ao = ffma2(xaO, v2.y, a2Ao);
                a2Be = ffma2(xbE, v2.x, a2Be);  a2Bo = ffma2(xbO, v2.y, a2Bo);
                a3Ae = ffma2(xaE, v3.x, a3Ae);  a3Ao = ffma2(xaO, v3.y, a3Ao);
                a3Be = ffma2(xbE, v3.x, a3Be);  a3Bo = ffma2(xbO, v3.y, a3Bo);
            }

            float lo, hi;
            float w0 = ww_s[j0 + 0], w1 = ww_s[j0 + 1];
            float w2 = ww_s[j0 + 2], w3 = ww_s[j0 + 3];

            unpack2(fadd2(a0Ae, a0Ao), lo, hi);
            float d0A = __fmaf_rn(-2.0f, __fadd_rn(lo, hi), w0);
            unpack2(fadd2(a1Ae, a1Ao), lo, hi);
            float d1A = __fmaf_rn(-2.0f, __fadd_rn(lo, hi), w1);
            unpack2(fadd2(a2Ae, a2Ao), lo, hi);
            float d2A = __fmaf_rn(-2.0f, __fadd_rn(lo, hi), w2);
            unpack2(fadd2(a3Ae, a3Ao), lo, hi);
            float d3A = __fmaf_rn(-2.0f, __fadd_rn(lo, hi), w3);
            unpack2(fadd2(a0Be, a0Bo), lo, hi);
            float d0B = __fmaf_rn(-2.0f, __fadd_rn(lo, hi), w0);
            unpack2(fadd2(a1Be, a1Bo), lo, hi);
            float d1B = __fmaf_rn(-2.0f, __fadd_rn(lo, hi), w1);
            unpack2(fadd2(a2Be, a2Bo), lo, hi);
            float d2B = __fmaf_rn(-2.0f, __fadd_rn(lo, hi), w2);
            unpack2(fadd2(a3Be, a3Bo), lo, hi);
            float d3B = __fmaf_rn(-2.0f, __fadd_rn(lo, hi), w3);

            // strict < ascending j => first-min tie-break (jnp.argmin)
            if (d0A < bestA) { bestA = d0A; biA = j0 + 0; }
            if (d1A < bestA) { bestA = d1A; biA = j0 + 1; }
            if (d2A < bestA) { bestA = d2A; biA = j0 + 2; }
            if (d3A < bestA) { bestA = d3A; biA = j0 + 3; }
            if (d0B < bestB) { bestB = d0B; biB = j0 + 0; }
            if (d1B < bestB) { bestB = d1B; biB = j0 + 1; }
            if (d2B < bestB) { bestB = d2B; biB = j0 + 2; }
            if (d3B < bestB) { bestB = d3B; biB = j0 + 3; }
        }

        out[OFF_ARG + (size_t)t0]       = (float)biA;
        out[OFF_ARG + (size_t)t0 + 256] = (float)biB;

        // quantized result from smem codebook
        {
            float* ro = out + (size_t)b0 * EMB_D * HWSZ + hw0;
            const float4* wrowA = (const float4*)(w_s + biA * EMB_D);
            const float4* wrowB = (const float4*)(w_s + biB * EMB_D);
            #pragma unroll
            for (int i = 0; i < EMB_D / 4; i++) {
                float4 va = wrowA[i];
                float4 vb = wrowB[i];
                ro[(4 * i + 0) * HWSZ]       = va.x;
                ro[(4 * i + 1) * HWSZ]       = va.y;
                ro[(4 * i + 2) * HWSZ]       = va.z;
                ro[(4 * i + 3) * HWSZ]       = va.w;
                ro[(4 * i + 0) * HWSZ + 256] = vb.x;
                ro[(4 * i + 1) * HWSZ + 256] = vb.y;
                ro[(4 * i + 2) * HWSZ + 256] = vb.z;
                ro[(4 * i + 3) * HWSZ + 256] = vb.w;
            }
        }

        // hist: warp-aggregated (one add per distinct index per warp)
        {
            unsigned int mA = __match_any_sync(0xFFFFFFFFu, biA);
            if ((int)(__ffs(mA) - 1) == lane)
                atomicAdd(&histR[biA], (float)__popc(mA));
            unsigned int mB = __match_any_sync(0xFFFFFFFFu, biB);
            if ((int)(__ffs(mB) - 1) == lane)
                atomicAdd(&histR[biB], (float)__popc(mB));
        }

        // esum: replicated accumulators (hot-address chains / NREP)
        #pragma unroll
        for (int i = 0; i < EMB_D / 2; i++) {
            float lo, hi;
            unpack2(xpa[i], lo, hi);
            atomicAdd(&esumR[(2 * i)     * N_EMB + biA], lo);
            atomicAdd(&esumR[(2 * i + 1) * N_EMB + biA], hi);
            unpack2(xpb[i], lo, hi);
            atomicAdd(&esumR[(2 * i)     * N_EMB + biB], lo);
            atomicAdd(&esumR[(2 * i + 1) * N_EMB + biB], hi);
        }
    }

    // ------- merged finalize: last CTA does the EMA update -------
    __threadfence();
    __syncthreads();
    if (tid == 0) s_rank = atomicAdd(&g_done, 1u);
    __syncthreads();
    if (s_rank == GRID_A - 1) {
        float* red = smem_dyn;

        const float DEC  = 0.99f;
        const float OMD  = (float)(1.0 - 0.99);
        const float EPSF = (float)1e-5;
        const float NEPS = (float)(N_EMB * 1e-5);

        float ncs0, ncs1;
        {
            float n0 = 0.0f, n1 = 0.0f;
            #pragma unroll
            for (int r = 0; r < NREP; r++) {
                n0 += g_histR[r][tid];
                n1 += g_histR[r][tid + 256];
            }
            if (n0 == 0.0f) n0 = 1.0f;
            if (n1 == 0.0f) n1 = 1.0f;
            ncs0 = __fadd_rn(__fmul_rn(DEC, cs_in[tid]), __fmul_rn(OMD, n0));
            ncs1 = __fadd_rn(__fmul_rn(DEC, cs_in[tid + 256]), __fmul_rn(OMD, n1));
        }

        __syncthreads();
        red[tid] = ncs0 + ncs1;
        __syncthreads();
        #pragma unroll
        for (int s = 128; s > 0; s >>= 1) {
            if (tid < s) red[tid] += red[tid + s];
            __syncthreads();
        }
        float n = red[0];

        float csn0 = __fmul_rn(__fdiv_rn(__fadd_rn(ncs0, EPSF),
                                         __fadd_rn(n, NEPS)), n);
        float csn1 = __fmul_rn(__fdiv_rn(__fadd_rn(ncs1, EPSF),
                                         __fadd_rn(n, NEPS)), n);

        out[OFF_CS + tid]       = ncs0;
        out[OFF_CS + tid + 256] = ncs1;

        for (int d = 0; d < EMB_D; d++) {
            int i0 = d * N_EMB + tid;
            int i1 = i0 + 256;
            float s0 = 0.0f, s1 = 0.0f;
            #pragma unroll
            for (int r = 0; r < NREP; r++) {
                s0 += g_esumR[r][i0];
                s1 += g_esumR[r][i1];
            }
            float e0 = __fadd_rn(__fmul_rn(DEC, ea_in[i0]), __fmul_rn(OMD, s0));
            float e1 = __fadd_rn(__fmul_rn(DEC, ea_in[i1]), __fmul_rn(OMD, s1));
            out[OFF_EA + i0] = e0;
            out[OFF_EA + i1] = e1;
            out[OFF_W  + i0] = __fdiv_rn(e0, csn0);
            out[OFF_W  + i1] = __fdiv_rn(e1, csn1);
        }
    }
}

// ---------------------------------------------------------------------------
extern "C" void kernel_launch(void* const* d_in, const int* in_sizes, int n_in,
                              void* d_out, int out_size) {
    const float* x  = (const float*)d_in[0];
    const float* w  = (const float*)d_in[1];
    const float* cs = (const float*)d_in[2];
    const float* ea = (const float*)d_in[3];
    float* out = (float*)d_out;

    cudaFuncSetAttribute(assign_kernel,
                         cudaFuncAttributeMaxDynamicSharedMemorySize, SMEM_BYTES);

    prep_kernel<<<128, 256>>>(w);
    assign_kernel<<<GRID_A, TPB, SMEM_BYTES>>>(x, cs, ea, out);
}